// round 15
// baseline (speedup 1.0000x reference)
#include <cuda_runtime.h>
#include <cuda_bf16.h>
#include <cuda_fp16.h>
#include <cstdint>

#define BB 8192
#define DD 1024
#define NTILES 4096
#define NCTA   304          // 2 CTAs/SM x 152 SMs (GB300)

// ---------------- scratch (device globals: no allocations allowed) -------------
__device__ __align__(16) uint8_t g_q8[BB * DD];   // 8 MB, e4m3, rows scaled x16
__device__ __align__(16) uint8_t g_p8[BB * DD];   // 8 MB
__device__ float g_mse_q[BB];
__device__ float g_mse_p[BB];
__device__ float g_sumexp[BB];
__device__ float g_diag[BB];

// =======================================================================
// Stage 1: per-row norm + MSE partial + fp8(e4m3) normalized write (x16).
// One warp per (tensor,row) task. grid = 2048, block = 256.
// =======================================================================
__device__ __forceinline__ uint32_t pack_e4m3x4(float x0, float x1, float x2, float x3)
{
    uint32_t w;
    asm("{\n\t.reg .b16 lo, hi;\n\t"
        "cvt.rn.satfinite.e4m3x2.f32 lo, %2, %1;\n\t"
        "cvt.rn.satfinite.e4m3x2.f32 hi, %4, %3;\n\t"
        "mov.b32 %0, {lo, hi};\n\t}"
        : "=r"(w) : "f"(x0), "f"(x1), "f"(x2), "f"(x3));
    return w;
}

__global__ void __launch_bounds__(256) prep_kernel(const float* __restrict__ sq,
                                                   const float* __restrict__ sp,
                                                   const float* __restrict__ tq,
                                                   const float* __restrict__ tp)
{
    if (blockIdx.x < 32) g_sumexp[blockIdx.x * 256 + threadIdx.x] = 0.f;

    const int lane = threadIdx.x & 31;
    const int task = blockIdx.x * 8 + (threadIdx.x >> 5);
    const int isP  = task >> 13;
    const int row  = task & 8191;

    const float* src = isP ? sp : sq;
    const float* tch = isP ? tp : tq;
    const float4* s4 = (const float4*)(src + (size_t)row * DD);
    const float4* t4 = (const float4*)(tch + (size_t)row * DD);

    float4 va[8];
    float nn = 0.f, mse = 0.f;
#pragma unroll
    for (int i = 0; i < 8; ++i) {
        float4 a = s4[i * 32 + lane]; va[i] = a;
        float4 t = t4[i * 32 + lane];
        nn += a.x * a.x + a.y * a.y + a.z * a.z + a.w * a.w;
        float dx = a.x - t.x, dy = a.y - t.y, dz = a.z - t.z, dw = a.w - t.w;
        mse += dx * dx + dy * dy + dz * dz + dw * dw;
    }
#pragma unroll
    for (int off = 16; off; off >>= 1) {
        nn  += __shfl_xor_sync(0xffffffffu, nn,  off);
        mse += __shfl_xor_sync(0xffffffffu, mse, off);
    }
    const float inv = 16.f / fmaxf(sqrtf(nn), 1e-8f);

    uint32_t* dst = (uint32_t*)((isP ? g_p8 : g_q8) + (size_t)row * DD);
#pragma unroll
    for (int i = 0; i < 8; ++i) {
        dst[i * 32 + lane] = pack_e4m3x4(va[i].x * inv, va[i].y * inv,
                                         va[i].z * inv, va[i].w * inv);
    }
    if (lane == 0) {
        if (isP) g_mse_p[row] = mse; else g_mse_q[row] = mse;
    }
}

// =======================================================================
// Stage 2: PERSISTENT fp8 e4m3 mma.sync (f16 accum). grid = 304 CTAs
// (2/SM), 128 threads = 4 warps (2 wr x 2 wc), warp tile 64x64,
// CTA tile 128x128. Each CTA owns a contiguous range of the 4096 tiles;
// the 3-stage cp.async pipeline flows ACROSS tile boundaries: no per-tile
// fill, no wave transitions. Register budget 256 (no spills).
// =======================================================================
#define NSTG        3
#define STAGE_BYTES 32768   // A 128x128B + B 128x128B
#define SUMS_OFF    (NSTG * STAGE_BYTES)
#define SMEM_SZ     (1024 + NSTG * STAGE_BYTES + 2048)

__device__ __forceinline__ void cp16(uint32_t dst, const void* src)
{
    asm volatile("cp.async.cg.shared.global [%0], [%1], 16;" :: "r"(dst), "l"(src));
}
__device__ __forceinline__ void cp_commit() { asm volatile("cp.async.commit_group;"); }

__device__ __forceinline__ void ldsm4(uint32_t* r, uint32_t addr)
{
    asm volatile("ldmatrix.sync.aligned.m8n8.x4.shared.b16 {%0,%1,%2,%3}, [%4];"
                 : "=r"(r[0]), "=r"(r[1]), "=r"(r[2]), "=r"(r[3]) : "r"(addr));
}

// fp8 mma, f16 accumulate: D/C = 2 x .f16x2 regs
__device__ __forceinline__ void mma8h(uint32_t* d, const uint32_t* a,
                                      uint32_t b0, uint32_t b1)
{
    asm volatile("mma.sync.aligned.m16n8k32.row.col.f16.e4m3.e4m3.f16 "
                 "{%0,%1}, {%2,%3,%4,%5}, {%6,%7}, {%0,%1};"
                 : "+r"(d[0]), "+r"(d[1])
                 : "r"(a[0]), "r"(a[1]), "r"(a[2]), "r"(a[3]), "r"(b0), "r"(b1));
}

// ---- packed f32x2 helpers ----
__device__ __forceinline__ unsigned long long pk2(float lo, float hi)
{
    unsigned long long d;
    asm("mov.b64 %0, {%1,%2};" : "=l"(d) : "r"(__float_as_uint(lo)), "r"(__float_as_uint(hi)));
    return d;
}
__device__ __forceinline__ unsigned long long fma2(unsigned long long a,
                                                   unsigned long long b,
                                                   unsigned long long c)
{
    unsigned long long d;
    asm("fma.rn.f32x2 %0, %1, %2, %3;" : "=l"(d) : "l"(a), "l"(b), "l"(c));
    return d;
}
__device__ __forceinline__ unsigned long long add2(unsigned long long a,
                                                   unsigned long long b)
{
    unsigned long long d;
    asm("add.rn.f32x2 %0, %1, %2;" : "=l"(d) : "l"(a), "l"(b));
    return d;
}
__device__ __forceinline__ float hsum2(unsigned long long v)
{
    uint32_t lo, hi;
    asm("mov.b64 {%0,%1}, %2;" : "=r"(lo), "=r"(hi) : "l"(v));
    return __uint_as_float(lo) + __uint_as_float(hi);
}
__device__ __forceinline__ unsigned long long rep2(float f) { return pk2(f, f); }

// exp(raw/256) on raw in [-280,280]: degree-8 Taylor, 1/256^k folded, packed x2
__device__ __forceinline__ unsigned long long exp_poly2(unsigned long long x)
{
    unsigned long long p = rep2(1.34452663e-24f);
    p = fma2(p, x, rep2(2.75357304e-21f));
    p = fma2(p, x, rep2(4.93432455e-18f));
    p = fma2(p, x, rep2(7.57912252e-15f));
    p = fma2(p, x, rep2(9.70127682e-12f));
    p = fma2(p, x, rep2(9.93410748e-9f));
    p = fma2(p, x, rep2(7.62939453e-6f));
    p = fma2(p, x, rep2(3.90625e-3f));
    p = fma2(p, x, rep2(1.0f));
    return p;
}

__global__ void __launch_bounds__(128, 2) lse_kernel()
{
    extern __shared__ char smem[];
    const int tid  = threadIdx.x;
    const int lane = tid & 31;
    const int wid  = tid >> 5;
    const int wr   = wid >> 1;      // warp-row: rows wr*64..+63
    const int wc   = wid & 1;       // warp-col: cols wc*64..+63
    const int gid  = lane >> 2;
    const int qid  = lane & 3;

    const uint32_t sb   = (uint32_t)__cvta_generic_to_shared(smem);
    const uint32_t stg0 = (sb + 1023u) & ~1023u;
    float* sums = (float*)(smem + (stg0 - sb) + SUMS_OFF);   // [128][2]

    // contiguous tile range for this CTA
    const int t0 = (int)(((long long)blockIdx.x       * NTILES) / NCTA);
    const int t1 = (int)(((long long)(blockIdx.x + 1) * NTILES) / NCTA);
    const int gA = t0 * 8, gB = t1 * 8;

    // load global-chunk g into stage si (tile = g>>3, kchunk = g&7)
    auto load_chunk = [&](int g, int si) {
        if (g < gB) {
            const int t  = g >> 3, cc = g & 7;
            const char* Ab = (const char*)g_q8 + (size_t)(t >> 6) * 128 * DD;
            const char* Bb = (const char*)g_p8 + (size_t)(t & 63) * 128 * DD;
            uint32_t stg = stg0 + (uint32_t)si * STAGE_BYTES;
#pragma unroll
            for (int i = 0; i < 16; ++i) {
                int flat = tid + i * 128;          // 0..2047
                int isB  = flat >> 10;
                int f    = flat & 1023;
                int r    = f >> 3, c16 = f & 7;
                uint32_t dst = stg + (uint32_t)(isB << 14)
                             + (uint32_t)(r * 128 + ((c16 ^ (r & 7)) << 4));
                const char* src = (isB ? Bb : Ab) + (size_t)r * DD + cc * 128 + c16 * 16;
                cp16(dst, src);
            }
        }
        cp_commit();
    };
    load_chunk(gA, 0); load_chunk(gA + 1, 1); load_chunk(gA + 2, 2);

    // f16x2 accumulators
    uint32_t acc[4][8][2];
#pragma unroll
    for (int mt = 0; mt < 4; ++mt)
#pragma unroll
        for (int nt = 0; nt < 8; ++nt) { acc[mt][nt][0] = 0u; acc[mt][nt][1] = 0u; }

    // ldmatrix lane->address invariants
    const int arow = wr * 64 + (lane & 15);                     // + mt*16
    const int aseg = lane >> 4;
    const int brow = wc * 64 + (lane & 7) + ((lane >> 4) << 3); // + pr*16
    const int bseg = (lane >> 3) & 1;

    int cs = 0;
    for (int g = gA; g < gB; ++g) {
        asm volatile("cp.async.wait_group 2;" ::: "memory");   // chunk g resident
        __syncthreads();

        const uint32_t stgA = stg0 + (uint32_t)cs * STAGE_BYTES;
        const uint32_t stgB = stgA + 16384;
#pragma unroll
        for (int ks = 0; ks < 4; ++ks) {
            uint32_t a[4][4];
#pragma unroll
            for (int mt = 0; mt < 4; ++mt) {
                int r = arow + mt * 16;
                ldsm4(a[mt], stgA + r * 128 + (((ks * 2 + aseg) ^ (r & 7)) << 4));
            }
#pragma unroll
            for (int pr = 0; pr < 4; ++pr) {
                int r = brow + pr * 16;
                uint32_t b[4];
                ldsm4(b, stgB + r * 128 + (((ks * 2 + bseg) ^ (r & 7)) << 4));
#pragma unroll
                for (int mt = 0; mt < 4; ++mt) {
                    mma8h(acc[mt][2 * pr],     a[mt], b[0], b[1]);
                    mma8h(acc[mt][2 * pr + 1], a[mt], b[2], b[3]);
                }
            }
        }
        __syncthreads();                 // all warps done with stage cs
        load_chunk(g + 3, cs);           // refill for chunk g+3 (may cross tiles)
        cs = (cs == 2) ? 0 : cs + 1;

        if ((g & 7) == 7) {
            // ---- tile epilogue: FFMA2 exp sums, diag, reduce, reset acc ----
            const int t  = g >> 3;
            const int rb = t >> 6, cb = t & 63;

            float rsum[4][2];
#pragma unroll
            for (int mt = 0; mt < 4; ++mt) {
                unsigned long long s0 = 0ull, s1 = 0ull;
#pragma unroll
                for (int nt = 0; nt < 8; ++nt) {
                    const float2 v0 = __half22float2(*(const half2*)&acc[mt][nt][0]);
                    const float2 v1 = __half22float2(*(const half2*)&acc[mt][nt][1]);
                    s0 = add2(s0, exp_poly2(pk2(v0.x, v0.y)));
                    s1 = add2(s1, exp_poly2(pk2(v1.x, v1.y)));
                }
                rsum[mt][0] = hsum2(s0);
                rsum[mt][1] = hsum2(s1);
            }

            if (rb == cb) {
#pragma unroll
                for (int mt = 0; mt < 4; ++mt)
#pragma unroll
                    for (int nt = 0; nt < 8; ++nt)
#pragma unroll
                        for (int h = 0; h < 2; ++h) {
                            const int rt = wr * 64 + mt * 16 + gid + h * 8;
                            const int c0 = wc * 64 + nt * 8 + qid * 2;
                            if (rt == c0 || rt == c0 + 1) {
                                const float2 v =
                                    __half22float2(*(const half2*)&acc[mt][nt][h]);
                                g_diag[rb * 128 + rt] =
                                    ((rt == c0) ? v.x : v.y) * (1.0f / 256.0f);
                            }
                        }
            }

#pragma unroll
            for (int mt = 0; mt < 4; ++mt)
#pragma unroll
                for (int nt = 0; nt < 8; ++nt) { acc[mt][nt][0] = 0u; acc[mt][nt][1] = 0u; }

#pragma unroll
            for (int off = 1; off < 4; off <<= 1)
#pragma unroll
                for (int mt = 0; mt < 4; ++mt) {
                    rsum[mt][0] += __shfl_xor_sync(0xffffffffu, rsum[mt][0], off);
                    rsum[mt][1] += __shfl_xor_sync(0xffffffffu, rsum[mt][1], off);
                }
            __syncthreads();             // prior tile's sums readers done
            if (qid == 0) {
#pragma unroll
                for (int mt = 0; mt < 4; ++mt) {
                    sums[(wr * 64 + mt * 16 + gid) * 2 + wc]     = rsum[mt][0];
                    sums[(wr * 64 + mt * 16 + gid + 8) * 2 + wc] = rsum[mt][1];
                }
            }
            __syncthreads();
            atomicAdd(&g_sumexp[rb * 128 + tid], sums[tid * 2] + sums[tid * 2 + 1]);
        }
    }
}

// =======================================================================
// Stage 3: final scalar.
// =======================================================================
__global__ void __launch_bounds__(1024) finalize_kernel(float* __restrict__ out)
{
    __shared__ float sa[1024], sb_[1024];
    float a = 0.f, b = 0.f;
    for (int i = threadIdx.x; i < BB; i += 1024) {
        a += g_mse_q[i] + g_mse_p[i];
        b += __logf(g_sumexp[i]) - g_diag[i];
    }
    sa[threadIdx.x] = a; sb_[threadIdx.x] = b;
    __syncthreads();
    for (int off = 512; off; off >>= 1) {
        if (threadIdx.x < off) {
            sa[threadIdx.x]  += sa[threadIdx.x + off];
            sb_[threadIdx.x] += sb_[threadIdx.x + off];
        }
        __syncthreads();
    }
    if (threadIdx.x == 0) {
        const float distill   = sa[0] / (2.f * (float)BB * (float)DD);
        const float retrieval = sb_[0] / (float)BB;
        out[0] = 0.5f * distill + 0.5f * retrieval;
    }
}

// =======================================================================
extern "C" void kernel_launch(void* const* d_in, const int* in_sizes, int n_in,
                              void* d_out, int out_size)
{
    (void)in_sizes; (void)n_in; (void)out_size;
    const float* sq = (const float*)d_in[0];
    const float* sp = (const float*)d_in[1];
    const float* tq = (const float*)d_in[2];
    const float* tp = (const float*)d_in[3];

    cudaFuncSetAttribute(lse_kernel, cudaFuncAttributeMaxDynamicSharedMemorySize, SMEM_SZ);

    prep_kernel<<<BB / 4, 256>>>(sq, sp, tq, tp);
    lse_kernel<<<NCTA, 128, SMEM_SZ>>>();
    finalize_kernel<<<1, 1024>>>((float*)d_out);
}

// round 16
// speedup vs baseline: 1.0634x; 1.0634x over previous
#include <cuda_runtime.h>
#include <cuda_bf16.h>
#include <cuda_fp16.h>
#include <cstdint>

#define BB 8192
#define DD 1024

// ---------------- scratch (device globals: no allocations allowed) -------------
__device__ __align__(16) uint8_t g_q8[BB * DD];   // 8 MB, e4m3, rows scaled x16
__device__ __align__(16) uint8_t g_p8[BB * DD];   // 8 MB
__device__ float g_mse_q[BB];
__device__ float g_mse_p[BB];
__device__ float g_sumexp[BB];
__device__ float g_diag[BB];

// =======================================================================
// Stage 1: per-row norm + MSE partial + fp8(e4m3) normalized write (x16).
// One warp per (tensor,row) task. grid = 2048, block = 256.
// =======================================================================
__device__ __forceinline__ uint32_t pack_e4m3x4(float x0, float x1, float x2, float x3)
{
    uint32_t w;
    asm("{\n\t.reg .b16 lo, hi;\n\t"
        "cvt.rn.satfinite.e4m3x2.f32 lo, %2, %1;\n\t"
        "cvt.rn.satfinite.e4m3x2.f32 hi, %4, %3;\n\t"
        "mov.b32 %0, {lo, hi};\n\t}"
        : "=r"(w) : "f"(x0), "f"(x1), "f"(x2), "f"(x3));
    return w;
}

__global__ void __launch_bounds__(256) prep_kernel(const float* __restrict__ sq,
                                                   const float* __restrict__ sp,
                                                   const float* __restrict__ tq,
                                                   const float* __restrict__ tp)
{
    if (blockIdx.x < 32) g_sumexp[blockIdx.x * 256 + threadIdx.x] = 0.f;

    const int lane = threadIdx.x & 31;
    const int task = blockIdx.x * 8 + (threadIdx.x >> 5);
    const int isP  = task >> 13;
    const int row  = task & 8191;

    const float* src = isP ? sp : sq;
    const float* tch = isP ? tp : tq;
    const float4* s4 = (const float4*)(src + (size_t)row * DD);
    const float4* t4 = (const float4*)(tch + (size_t)row * DD);

    float4 va[8];
    float nn = 0.f, mse = 0.f;
#pragma unroll
    for (int i = 0; i < 8; ++i) {
        float4 a = s4[i * 32 + lane]; va[i] = a;
        float4 t = t4[i * 32 + lane];
        nn += a.x * a.x + a.y * a.y + a.z * a.z + a.w * a.w;
        float dx = a.x - t.x, dy = a.y - t.y, dz = a.z - t.z, dw = a.w - t.w;
        mse += dx * dx + dy * dy + dz * dz + dw * dw;
    }
#pragma unroll
    for (int off = 16; off; off >>= 1) {
        nn  += __shfl_xor_sync(0xffffffffu, nn,  off);
        mse += __shfl_xor_sync(0xffffffffu, mse, off);
    }
    const float inv = 16.f / fmaxf(sqrtf(nn), 1e-8f);

    uint32_t* dst = (uint32_t*)((isP ? g_p8 : g_q8) + (size_t)row * DD);
#pragma unroll
    for (int i = 0; i < 8; ++i) {
        dst[i * 32 + lane] = pack_e4m3x4(va[i].x * inv, va[i].y * inv,
                                         va[i].z * inv, va[i].w * inv);
    }
    if (lane == 0) {
        if (isP) g_mse_p[row] = mse; else g_mse_q[row] = mse;
    }
}

// =======================================================================
// Stage 2: fp8 e4m3 mma.sync (f16 accum), 128x128 tile/CTA, 128 threads
// = 4 warps (2 wr x 2 wc), warp tile 64x64. K in 8 chunks of 128B,
// 3-stage cp.async, 2 CTAs/SM (R9 base = empirical best).
// NEW: ldsm fragments double-buffered across ks steps — ldsm for ks+1
// issues during ks's 32-mma burst, hiding the shared-load latency.
// =======================================================================
#define NSTG        3
#define STAGE_BYTES 32768   // A 128x128B + B 128x128B
#define SUMS_OFF    (NSTG * STAGE_BYTES)
#define SMEM_SZ     (1024 + NSTG * STAGE_BYTES + 2048)

__device__ __forceinline__ void cp16(uint32_t dst, const void* src)
{
    asm volatile("cp.async.cg.shared.global [%0], [%1], 16;" :: "r"(dst), "l"(src));
}
__device__ __forceinline__ void cp_commit() { asm volatile("cp.async.commit_group;"); }

__device__ __forceinline__ void ldsm4(uint32_t* r, uint32_t addr)
{
    asm volatile("ldmatrix.sync.aligned.m8n8.x4.shared.b16 {%0,%1,%2,%3}, [%4];"
                 : "=r"(r[0]), "=r"(r[1]), "=r"(r[2]), "=r"(r[3]) : "r"(addr));
}

// fp8 mma, f16 accumulate: D/C = 2 x .f16x2 regs
__device__ __forceinline__ void mma8h(uint32_t* d, const uint32_t* a,
                                      uint32_t b0, uint32_t b1)
{
    asm volatile("mma.sync.aligned.m16n8k32.row.col.f16.e4m3.e4m3.f16 "
                 "{%0,%1}, {%2,%3,%4,%5}, {%6,%7}, {%0,%1};"
                 : "+r"(d[0]), "+r"(d[1])
                 : "r"(a[0]), "r"(a[1]), "r"(a[2]), "r"(a[3]), "r"(b0), "r"(b1));
}

// ---- packed f32x2 helpers ----
__device__ __forceinline__ unsigned long long pk2(float lo, float hi)
{
    unsigned long long d;
    asm("mov.b64 %0, {%1,%2};" : "=l"(d) : "r"(__float_as_uint(lo)), "r"(__float_as_uint(hi)));
    return d;
}
__device__ __forceinline__ unsigned long long fma2(unsigned long long a,
                                                   unsigned long long b,
                                                   unsigned long long c)
{
    unsigned long long d;
    asm("fma.rn.f32x2 %0, %1, %2, %3;" : "=l"(d) : "l"(a), "l"(b), "l"(c));
    return d;
}
__device__ __forceinline__ unsigned long long add2(unsigned long long a,
                                                   unsigned long long b)
{
    unsigned long long d;
    asm("add.rn.f32x2 %0, %1, %2;" : "=l"(d) : "l"(a), "l"(b));
    return d;
}
__device__ __forceinline__ float hsum2(unsigned long long v)
{
    uint32_t lo, hi;
    asm("mov.b64 {%0,%1}, %2;" : "=r"(lo), "=r"(hi) : "l"(v));
    return __uint_as_float(lo) + __uint_as_float(hi);
}
__device__ __forceinline__ unsigned long long rep2(float f) { return pk2(f, f); }

// exp(raw/256) on raw in [-280,280]: degree-8 Taylor, 1/256^k folded, packed x2
__device__ __forceinline__ unsigned long long exp_poly2(unsigned long long x)
{
    unsigned long long p = rep2(1.34452663e-24f);
    p = fma2(p, x, rep2(2.75357304e-21f));
    p = fma2(p, x, rep2(4.93432455e-18f));
    p = fma2(p, x, rep2(7.57912252e-15f));
    p = fma2(p, x, rep2(9.70127682e-12f));
    p = fma2(p, x, rep2(9.93410748e-9f));
    p = fma2(p, x, rep2(7.62939453e-6f));
    p = fma2(p, x, rep2(3.90625e-3f));
    p = fma2(p, x, rep2(1.0f));
    return p;
}

__global__ void __launch_bounds__(128, 2) lse_kernel()
{
    extern __shared__ char smem[];
    const int tid  = threadIdx.x;
    const int lane = tid & 31;
    const int wid  = tid >> 5;
    const int rb   = blockIdx.x & 63;
    const int cb   = blockIdx.x >> 6;
    const int wr   = wid >> 1;      // warp-row: rows wr*64..+63
    const int wc   = wid & 1;       // warp-col: cols wc*64..+63
    const int gid  = lane >> 2;
    const int qid  = lane & 3;

    const uint32_t sb   = (uint32_t)__cvta_generic_to_shared(smem);
    const uint32_t stg0 = (sb + 1023u) & ~1023u;
    float* sums = (float*)(smem + (stg0 - sb) + SUMS_OFF);   // [128][2]

    const char* Abase = (const char*)g_q8 + (size_t)rb * 128 * DD;
    const char* Bbase = (const char*)g_p8 + (size_t)cb * 128 * DD;

    // chunk cc: A[128 x 128B] + B[128 x 128B], XOR-swizzled 16B lanes
    auto load_chunk = [&](int cc) {
        if (cc < 8) {
            uint32_t stg = stg0 + (uint32_t)(cc % NSTG) * STAGE_BYTES;
#pragma unroll
            for (int i = 0; i < 16; ++i) {
                int flat = tid + i * 128;          // 0..2047
                int isB  = flat >> 10;
                int f    = flat & 1023;
                int r    = f >> 3, c16 = f & 7;
                uint32_t dst = stg + (uint32_t)(isB << 14)
                             + (uint32_t)(r * 128 + ((c16 ^ (r & 7)) << 4));
                const char* src = (isB ? Bbase : Abase) + (size_t)r * DD + cc * 128 + c16 * 16;
                cp16(dst, src);
            }
        }
        cp_commit();
    };
    load_chunk(0); load_chunk(1); load_chunk(2);

    // f16x2 accumulators: acc[mt][nt][h]
    uint32_t acc[4][8][2];
#pragma unroll
    for (int mt = 0; mt < 4; ++mt)
#pragma unroll
        for (int nt = 0; nt < 8; ++nt) { acc[mt][nt][0] = 0u; acc[mt][nt][1] = 0u; }

    // ldmatrix lane->address invariants
    const int arow = wr * 64 + (lane & 15);                     // + mt*16
    const int aseg = lane >> 4;
    const int brow = wc * 64 + (lane & 7) + ((lane >> 4) << 3); // + pr*16
    const int bseg = (lane >> 3) & 1;

    for (int c = 0; c < 8; ++c) {
        asm volatile("cp.async.wait_group 2;" ::: "memory");   // chunk c resident
        __syncthreads();

        const uint32_t stgA = stg0 + (uint32_t)(c % NSTG) * STAGE_BYTES;
        const uint32_t stgB = stgA + 16384;

        // fragment double buffers: [2][4][4] each (A and B)
        uint32_t a[2][4][4], b[2][4][4];

        auto ld_frags = [&](int ks, int buf) {
#pragma unroll
            for (int mt = 0; mt < 4; ++mt) {
                int r = arow + mt * 16;
                ldsm4(a[buf][mt], stgA + r * 128 + (((ks * 2 + aseg) ^ (r & 7)) << 4));
            }
#pragma unroll
            for (int pr = 0; pr < 4; ++pr) {
                int r = brow + pr * 16;
                ldsm4(b[buf][pr], stgB + r * 128 + (((ks * 2 + bseg) ^ (r & 7)) << 4));
            }
        };

        ld_frags(0, 0);
#pragma unroll
        for (int ks = 0; ks < 4; ++ks) {
            const int cur = ks & 1;
            if (ks < 3) ld_frags(ks + 1, cur ^ 1);   // hide ldsm under mma burst
#pragma unroll
            for (int pr = 0; pr < 4; ++pr)
#pragma unroll
                for (int mt = 0; mt < 4; ++mt) {
                    mma8h(acc[mt][2 * pr],     a[cur][mt], b[cur][pr][0], b[cur][pr][1]);
                    mma8h(acc[mt][2 * pr + 1], a[cur][mt], b[cur][pr][2], b[cur][pr][3]);
                }
        }
        __syncthreads();          // all warps done with stage c before overwrite
        load_chunk(c + 3);
    }

    // ---- epilogue: packed FFMA2 exp(raw/256) sums + diagonal capture ----
    float rsum[4][2];
#pragma unroll
    for (int mt = 0; mt < 4; ++mt) {
        unsigned long long s0 = 0ull, s1 = 0ull;
#pragma unroll
        for (int nt = 0; nt < 8; ++nt) {
            const float2 v0 = __half22float2(*(const half2*)&acc[mt][nt][0]);
            const float2 v1 = __half22float2(*(const half2*)&acc[mt][nt][1]);
            s0 = add2(s0, exp_poly2(pk2(v0.x, v0.y)));
            s1 = add2(s1, exp_poly2(pk2(v1.x, v1.y)));
        }
        rsum[mt][0] = hsum2(s0);
        rsum[mt][1] = hsum2(s1);
    }

    if (rb == cb) {   // only diagonal CTAs hold diagonal elements
#pragma unroll
        for (int mt = 0; mt < 4; ++mt)
#pragma unroll
            for (int nt = 0; nt < 8; ++nt)
#pragma unroll
                for (int h = 0; h < 2; ++h) {
                    const int rt = wr * 64 + mt * 16 + gid + h * 8;
                    const int c0 = wc * 64 + nt * 8 + qid * 2;
                    if (rt == c0 || rt == c0 + 1) {
                        const float2 v = __half22float2(*(const half2*)&acc[mt][nt][h]);
                        g_diag[rb * 128 + rt] =
                            ((rt == c0) ? v.x : v.y) * (1.0f / 256.0f);
                    }
                }
    }

#pragma unroll
    for (int off = 1; off < 4; off <<= 1)
#pragma unroll
        for (int mt = 0; mt < 4; ++mt) {
            rsum[mt][0] += __shfl_xor_sync(0xffffffffu, rsum[mt][0], off);
            rsum[mt][1] += __shfl_xor_sync(0xffffffffu, rsum[mt][1], off);
        }
    __syncthreads();            // stage buffers dead; sums region is fresh
    if (qid == 0) {
#pragma unroll
        for (int mt = 0; mt < 4; ++mt) {
            sums[(wr * 64 + mt * 16 + gid) * 2 + wc]     = rsum[mt][0];
            sums[(wr * 64 + mt * 16 + gid + 8) * 2 + wc] = rsum[mt][1];
        }
    }
    __syncthreads();
    // 128 threads: one row each
    {
        const float v = sums[tid * 2] + sums[tid * 2 + 1];
        atomicAdd(&g_sumexp[rb * 128 + tid], v);
    }
}

// =======================================================================
// Stage 3: final scalar.
// =======================================================================
__global__ void __launch_bounds__(1024) finalize_kernel(float* __restrict__ out)
{
    __shared__ float sa[1024], sb_[1024];
    float a = 0.f, b = 0.f;
    for (int i = threadIdx.x; i < BB; i += 1024) {
        a += g_mse_q[i] + g_mse_p[i];
        b += __logf(g_sumexp[i]) - g_diag[i];
    }
    sa[threadIdx.x] = a; sb_[threadIdx.x] = b;
    __syncthreads();
    for (int off = 512; off; off >>= 1) {
        if (threadIdx.x < off) {
            sa[threadIdx.x]  += sa[threadIdx.x + off];
            sb_[threadIdx.x] += sb_[threadIdx.x + off];
        }
        __syncthreads();
    }
    if (threadIdx.x == 0) {
        const float distill   = sa[0] / (2.f * (float)BB * (float)DD);
        const float retrieval = sb_[0] / (float)BB;
        out[0] = 0.5f * distill + 0.5f * retrieval;
    }
}

// =======================================================================
extern "C" void kernel_launch(void* const* d_in, const int* in_sizes, int n_in,
                              void* d_out, int out_size)
{
    (void)in_sizes; (void)n_in; (void)out_size;
    const float* sq = (const float*)d_in[0];
    const float* sp = (const float*)d_in[1];
    const float* tq = (const float*)d_in[2];
    const float* tp = (const float*)d_in[3];

    cudaFuncSetAttribute(lse_kernel, cudaFuncAttributeMaxDynamicSharedMemorySize, SMEM_SZ);

    prep_kernel<<<BB / 4, 256>>>(sq, sp, tq, tp);
    lse_kernel<<<4096, 128, SMEM_SZ>>>();
    finalize_kernel<<<1, 1024>>>((float*)d_out);
}

// round 17
// speedup vs baseline: 1.1299x; 1.0625x over previous
#include <cuda_runtime.h>
#include <cuda_bf16.h>
#include <cuda_fp16.h>
#include <cstdint>

#define BB 8192
#define DD 1024

// ---------------- scratch (device globals: no allocations allowed) -------------
__device__ __align__(16) uint8_t g_q8[BB * DD];   // 8 MB, e4m3, rows scaled x16
__device__ __align__(16) uint8_t g_p8[BB * DD];   // 8 MB
__device__ float g_mse_q[BB];
__device__ float g_mse_p[BB];
__device__ float g_sumexp[BB];
__device__ float g_diag[BB];

// =======================================================================
// Stage 1: per-row norm + MSE partial + fp8(e4m3) normalized write (x16).
// One warp per (tensor,row) task. grid = 2048, block = 256.
// Inputs read once -> __ldcs (evict-first) keeps L2 for the fp8 outputs.
// =======================================================================
__device__ __forceinline__ uint32_t pack_e4m3x4(float x0, float x1, float x2, float x3)
{
    uint32_t w;
    asm("{\n\t.reg .b16 lo, hi;\n\t"
        "cvt.rn.satfinite.e4m3x2.f32 lo, %2, %1;\n\t"
        "cvt.rn.satfinite.e4m3x2.f32 hi, %4, %3;\n\t"
        "mov.b32 %0, {lo, hi};\n\t}"
        : "=r"(w) : "f"(x0), "f"(x1), "f"(x2), "f"(x3));
    return w;
}

__global__ void __launch_bounds__(256) prep_kernel(const float* __restrict__ sq,
                                                   const float* __restrict__ sp,
                                                   const float* __restrict__ tq,
                                                   const float* __restrict__ tp)
{
    if (blockIdx.x < 32) g_sumexp[blockIdx.x * 256 + threadIdx.x] = 0.f;

    const int lane = threadIdx.x & 31;
    const int task = blockIdx.x * 8 + (threadIdx.x >> 5);
    const int isP  = task >> 13;
    const int row  = task & 8191;

    const float* src = isP ? sp : sq;
    const float* tch = isP ? tp : tq;
    const float4* s4 = (const float4*)(src + (size_t)row * DD);
    const float4* t4 = (const float4*)(tch + (size_t)row * DD);

    float4 va[8];
    float nn = 0.f, mse = 0.f;
#pragma unroll
    for (int i = 0; i < 8; ++i) {
        float4 a = __ldcs(&s4[i * 32 + lane]); va[i] = a;
        float4 t = __ldcs(&t4[i * 32 + lane]);
        nn += a.x * a.x + a.y * a.y + a.z * a.z + a.w * a.w;
        float dx = a.x - t.x, dy = a.y - t.y, dz = a.z - t.z, dw = a.w - t.w;
        mse += dx * dx + dy * dy + dz * dz + dw * dw;
    }
#pragma unroll
    for (int off = 16; off; off >>= 1) {
        nn  += __shfl_xor_sync(0xffffffffu, nn,  off);
        mse += __shfl_xor_sync(0xffffffffu, mse, off);
    }
    const float inv = 16.f / fmaxf(sqrtf(nn), 1e-8f);

    uint32_t* dst = (uint32_t*)((isP ? g_p8 : g_q8) + (size_t)row * DD);
#pragma unroll
    for (int i = 0; i < 8; ++i) {
        dst[i * 32 + lane] = pack_e4m3x4(va[i].x * inv, va[i].y * inv,
                                         va[i].z * inv, va[i].w * inv);
    }
    if (lane == 0) {
        if (isP) g_mse_p[row] = mse; else g_mse_q[row] = mse;
    }
}

// =======================================================================
// Stage 2: fp8 e4m3 mma.sync (f16 accum), 128x128 tile/CTA, 128 threads
// = 4 warps (2 wr x 2 wc), warp tile 64x64. K in 8 chunks of 128B,
// 3-stage cp.async, 2 CTAs/SM (R9 base = empirical best).
// Micro-change vs R9: all 4 B ldsm hoisted before the 32-mma burst (+12 regs).
// =======================================================================
#define NSTG        3
#define STAGE_BYTES 32768   // A 128x128B + B 128x128B
#define SUMS_OFF    (NSTG * STAGE_BYTES)
#define SMEM_SZ     (1024 + NSTG * STAGE_BYTES + 2048)

__device__ __forceinline__ void cp16(uint32_t dst, const void* src)
{
    asm volatile("cp.async.cg.shared.global [%0], [%1], 16;" :: "r"(dst), "l"(src));
}
__device__ __forceinline__ void cp_commit() { asm volatile("cp.async.commit_group;"); }

__device__ __forceinline__ void ldsm4(uint32_t* r, uint32_t addr)
{
    asm volatile("ldmatrix.sync.aligned.m8n8.x4.shared.b16 {%0,%1,%2,%3}, [%4];"
                 : "=r"(r[0]), "=r"(r[1]), "=r"(r[2]), "=r"(r[3]) : "r"(addr));
}

// fp8 mma, f16 accumulate: D/C = 2 x .f16x2 regs
__device__ __forceinline__ void mma8h(uint32_t* d, const uint32_t* a,
                                      uint32_t b0, uint32_t b1)
{
    asm volatile("mma.sync.aligned.m16n8k32.row.col.f16.e4m3.e4m3.f16 "
                 "{%0,%1}, {%2,%3,%4,%5}, {%6,%7}, {%0,%1};"
                 : "+r"(d[0]), "+r"(d[1])
                 : "r"(a[0]), "r"(a[1]), "r"(a[2]), "r"(a[3]), "r"(b0), "r"(b1));
}

// ---- packed f32x2 helpers ----
__device__ __forceinline__ unsigned long long pk2(float lo, float hi)
{
    unsigned long long d;
    asm("mov.b64 %0, {%1,%2};" : "=l"(d) : "r"(__float_as_uint(lo)), "r"(__float_as_uint(hi)));
    return d;
}
__device__ __forceinline__ unsigned long long fma2(unsigned long long a,
                                                   unsigned long long b,
                                                   unsigned long long c)
{
    unsigned long long d;
    asm("fma.rn.f32x2 %0, %1, %2, %3;" : "=l"(d) : "l"(a), "l"(b), "l"(c));
    return d;
}
__device__ __forceinline__ unsigned long long add2(unsigned long long a,
                                                   unsigned long long b)
{
    unsigned long long d;
    asm("add.rn.f32x2 %0, %1, %2;" : "=l"(d) : "l"(a), "l"(b));
    return d;
}
__device__ __forceinline__ float hsum2(unsigned long long v)
{
    uint32_t lo, hi;
    asm("mov.b64 {%0,%1}, %2;" : "=r"(lo), "=r"(hi) : "l"(v));
    return __uint_as_float(lo) + __uint_as_float(hi);
}
__device__ __forceinline__ unsigned long long rep2(float f) { return pk2(f, f); }

// exp(raw/256) on raw in [-280,280]: degree-8 Taylor, 1/256^k folded, packed x2
__device__ __forceinline__ unsigned long long exp_poly2(unsigned long long x)
{
    unsigned long long p = rep2(1.34452663e-24f);
    p = fma2(p, x, rep2(2.75357304e-21f));
    p = fma2(p, x, rep2(4.93432455e-18f));
    p = fma2(p, x, rep2(7.57912252e-15f));
    p = fma2(p, x, rep2(9.70127682e-12f));
    p = fma2(p, x, rep2(9.93410748e-9f));
    p = fma2(p, x, rep2(7.62939453e-6f));
    p = fma2(p, x, rep2(3.90625e-3f));
    p = fma2(p, x, rep2(1.0f));
    return p;
}

__global__ void __launch_bounds__(128, 2) lse_kernel()
{
    extern __shared__ char smem[];
    const int tid  = threadIdx.x;
    const int lane = tid & 31;
    const int wid  = tid >> 5;
    const int rb   = blockIdx.x & 63;
    const int cb   = blockIdx.x >> 6;
    const int wr   = wid >> 1;      // warp-row: rows wr*64..+63
    const int wc   = wid & 1;       // warp-col: cols wc*64..+63
    const int gid  = lane >> 2;
    const int qid  = lane & 3;

    const uint32_t sb   = (uint32_t)__cvta_generic_to_shared(smem);
    const uint32_t stg0 = (sb + 1023u) & ~1023u;
    float* sums = (float*)(smem + (stg0 - sb) + SUMS_OFF);   // [128][2]

    const char* Abase = (const char*)g_q8 + (size_t)rb * 128 * DD;
    const char* Bbase = (const char*)g_p8 + (size_t)cb * 128 * DD;

    // chunk cc: A[128 x 128B] + B[128 x 128B], XOR-swizzled 16B lanes
    auto load_chunk = [&](int cc) {
        if (cc < 8) {
            uint32_t stg = stg0 + (uint32_t)(cc % NSTG) * STAGE_BYTES;
#pragma unroll
            for (int i = 0; i < 16; ++i) {
                int flat = tid + i * 128;          // 0..2047
                int isB  = flat >> 10;
                int f    = flat & 1023;
                int r    = f >> 3, c16 = f & 7;
                uint32_t dst = stg + (uint32_t)(isB << 14)
                             + (uint32_t)(r * 128 + ((c16 ^ (r & 7)) << 4));
                const char* src = (isB ? Bbase : Abase) + (size_t)r * DD + cc * 128 + c16 * 16;
                cp16(dst, src);
            }
        }
        cp_commit();
    };
    load_chunk(0); load_chunk(1); load_chunk(2);

    // f16x2 accumulators: acc[mt][nt][h], h: reg0=row gid, reg1=row gid+8
    uint32_t acc[4][8][2];
#pragma unroll
    for (int mt = 0; mt < 4; ++mt)
#pragma unroll
        for (int nt = 0; nt < 8; ++nt) { acc[mt][nt][0] = 0u; acc[mt][nt][1] = 0u; }

    // ldmatrix lane->address invariants
    const int arow = wr * 64 + (lane & 15);                     // + mt*16
    const int aseg = lane >> 4;
    const int brow = wc * 64 + (lane & 7) + ((lane >> 4) << 3); // + pr*16
    const int bseg = (lane >> 3) & 1;

    for (int c = 0; c < 8; ++c) {
        asm volatile("cp.async.wait_group 2;" ::: "memory");   // chunk c resident
        __syncthreads();

        const uint32_t stgA = stg0 + (uint32_t)(c % NSTG) * STAGE_BYTES;
        const uint32_t stgB = stgA + 16384;
#pragma unroll
        for (int ks = 0; ks < 4; ++ks) {
            uint32_t a[4][4], b[4][4];
#pragma unroll
            for (int mt = 0; mt < 4; ++mt) {
                int r = arow + mt * 16;
                ldsm4(a[mt], stgA + r * 128 + (((ks * 2 + aseg) ^ (r & 7)) << 4));
            }
#pragma unroll
            for (int pr = 0; pr < 4; ++pr) {
                int r = brow + pr * 16;
                ldsm4(b[pr], stgB + r * 128 + (((ks * 2 + bseg) ^ (r & 7)) << 4));
            }
#pragma unroll
            for (int pr = 0; pr < 4; ++pr)
#pragma unroll
                for (int mt = 0; mt < 4; ++mt) {
                    mma8h(acc[mt][2 * pr],     a[mt], b[pr][0], b[pr][1]);
                    mma8h(acc[mt][2 * pr + 1], a[mt], b[pr][2], b[pr][3]);
                }
        }
        __syncthreads();          // all warps done with stage c before overwrite
        load_chunk(c + 3);
    }

    // ---- epilogue: packed FFMA2 exp(raw/256) sums + diagonal capture ----
    float rsum[4][2];
#pragma unroll
    for (int mt = 0; mt < 4; ++mt) {
        unsigned long long s0 = 0ull, s1 = 0ull;
#pragma unroll
        for (int nt = 0; nt < 8; ++nt) {
            const float2 v0 = __half22float2(*(const half2*)&acc[mt][nt][0]);
            const float2 v1 = __half22float2(*(const half2*)&acc[mt][nt][1]);
            s0 = add2(s0, exp_poly2(pk2(v0.x, v0.y)));
            s1 = add2(s1, exp_poly2(pk2(v1.x, v1.y)));
        }
        rsum[mt][0] = hsum2(s0);
        rsum[mt][1] = hsum2(s1);
    }

    if (rb == cb) {   // only diagonal CTAs hold diagonal elements
#pragma unroll
        for (int mt = 0; mt < 4; ++mt)
#pragma unroll
            for (int nt = 0; nt < 8; ++nt)
#pragma unroll
                for (int h = 0; h < 2; ++h) {
                    const int rt = wr * 64 + mt * 16 + gid + h * 8;
                    const int c0 = wc * 64 + nt * 8 + qid * 2;
                    if (rt == c0 || rt == c0 + 1) {
                        const float2 v = __half22float2(*(const half2*)&acc[mt][nt][h]);
                        g_diag[rb * 128 + rt] =
                            ((rt == c0) ? v.x : v.y) * (1.0f / 256.0f);
                    }
                }
    }

#pragma unroll
    for (int off = 1; off < 4; off <<= 1)
#pragma unroll
        for (int mt = 0; mt < 4; ++mt) {
            rsum[mt][0] += __shfl_xor_sync(0xffffffffu, rsum[mt][0], off);
            rsum[mt][1] += __shfl_xor_sync(0xffffffffu, rsum[mt][1], off);
        }
    __syncthreads();            // stage buffers dead; sums region is fresh
    if (qid == 0) {
#pragma unroll
        for (int mt = 0; mt < 4; ++mt) {
            sums[(wr * 64 + mt * 16 + gid) * 2 + wc]     = rsum[mt][0];
            sums[(wr * 64 + mt * 16 + gid + 8) * 2 + wc] = rsum[mt][1];
        }
    }
    __syncthreads();
    // 128 threads: one row each
    {
        const float v = sums[tid * 2] + sums[tid * 2 + 1];
        atomicAdd(&g_sumexp[rb * 128 + tid], v);
    }
}

// =======================================================================
// Stage 3: final scalar.
// =======================================================================
__global__ void __launch_bounds__(1024) finalize_kernel(float* __restrict__ out)
{
    __shared__ float sa[1024], sb_[1024];
    float a = 0.f, b = 0.f;
    for (int i = threadIdx.x; i < BB; i += 1024) {
        a += g_mse_q[i] + g_mse_p[i];
        b += __logf(g_sumexp[i]) - g_diag[i];
    }
    sa[threadIdx.x] = a; sb_[threadIdx.x] = b;
    __syncthreads();
    for (int off = 512; off; off >>= 1) {
        if (threadIdx.x < off) {
            sa[threadIdx.x]  += sa[threadIdx.x + off];
            sb_[threadIdx.x] += sb_[threadIdx.x + off];
        }
        __syncthreads();
    }
    if (threadIdx.x == 0) {
        const float distill   = sa[0] / (2.f * (float)BB * (float)DD);
        const float retrieval = sb_[0] / (float)BB;
        out[0] = 0.5f * distill + 0.5f * retrieval;
    }
}

// =======================================================================
extern "C" void kernel_launch(void* const* d_in, const int* in_sizes, int n_in,
                              void* d_out, int out_size)
{
    (void)in_sizes; (void)n_in; (void)out_size;
    const float* sq = (const float*)d_in[0];
    const float* sp = (const float*)d_in[1];
    const float* tq = (const float*)d_in[2];
    const float* tp = (const float*)d_in[3];

    cudaFuncSetAttribute(lse_kernel, cudaFuncAttributeMaxDynamicSharedMemorySize, SMEM_SZ);

    prep_kernel<<<BB / 4, 256>>>(sq, sp, tq, tp);
    lse_kernel<<<4096, 128, SMEM_SZ>>>();
    finalize_kernel<<<1, 1024>>>((float*)d_out);
}